// round 1
// baseline (speedup 1.0000x reference)
#include <cuda_runtime.h>

#define B_    4
#define CIN_  256
#define H_    64
#define W_    64
#define P_    4096          // H*W
#define K_    9
#define RDIM  2304          // CIN*K
#define COUT_ 256
#define NTOT  16384         // B*P

// 151 MB scratch for the im2col matrix: cols[r][n], r = c*9+k, n = b*4096+p
__device__ float g_cols[RDIM * NTOT];

// ---------------------------------------------------------------------------
// Kernel 1: fused sampling + im2col.
// Each thread owns one (b, k, p): computes the 4 bilinear corners + weights
// once, then loops the 256 channels (gathers are L1/L2-local, writes coalesced).
// ---------------------------------------------------------------------------
__global__ void im2col_kernel(const float* __restrict__ x,
                              const float* __restrict__ offset,
                              const float* __restrict__ mask) {
    int p = blockIdx.x * blockDim.x + threadIdx.x;   // 0..4095
    int k = blockIdx.y;                              // 0..8
    int b = blockIdx.z;                              // 0..3
    int oy = p >> 6, ox = p & 63;
    int kh = k / 3, kw = k - kh * 3;

    // offset channel layout: ch = k*2 + {0:dy, 1:dx}
    const float* offb = offset + (b * 18 + 2 * k) * P_;
    float dy = offb[p];
    float dx = offb[P_ + p];
    float m  = mask[(b * 9 + k) * P_ + p];

    float sy = (float)(oy - 1 + kh) + dy;
    float sx = (float)(ox - 1 + kw) + dx;
    float y0f = floorf(sy), x0f = floorf(sx);
    float wy = sy - y0f,    wx = sx - x0f;
    int y0 = (int)y0f, x0 = (int)x0f;
    int y1 = y0 + 1,   x1 = x0 + 1;

    bool vy0 = ((unsigned)y0 < 64u), vy1 = ((unsigned)y1 < 64u);
    bool vx0 = ((unsigned)x0 < 64u), vx1 = ((unsigned)x1 < 64u);
    int cy0 = min(max(y0, 0), 63), cy1 = min(max(y1, 0), 63);
    int cx0 = min(max(x0, 0), 63), cx1 = min(max(x1, 0), 63);
    int i00 = cy0 * 64 + cx0, i01 = cy0 * 64 + cx1;
    int i10 = cy1 * 64 + cx0, i11 = cy1 * 64 + cx1;

    float w00 = (1.f - wy) * (1.f - wx) * m; if (!(vy0 && vx0)) w00 = 0.f;
    float w01 = (1.f - wy) * wx * m;         if (!(vy0 && vx1)) w01 = 0.f;
    float w10 = wy * (1.f - wx) * m;         if (!(vy1 && vx0)) w10 = 0.f;
    float w11 = wy * wx * m;                 if (!(vy1 && vx1)) w11 = 0.f;

    const float* xb = x + b * (CIN_ * P_);
    float* cb = g_cols + k * NTOT + b * P_ + p;

    #pragma unroll 4
    for (int c = 0; c < CIN_; c++) {
        const float* xp = xb + c * P_;
        float v = w00 * __ldg(xp + i00) + w01 * __ldg(xp + i01)
                + w10 * __ldg(xp + i10) + w11 * __ldg(xp + i11);
        cb[c * (K_ * NTOT)] = v;
    }
}

// ---------------------------------------------------------------------------
// Kernel 2: SGEMM  C[256 x 16384] = W[256 x 2304] * cols[2304 x 16384] + bias
// 128x128 block tile, BK=8, 256 threads, 8x8 microtile, double-buffered smem.
// Inner product uses packed fma.rn.f32x2 (2 fp32/instr on the fma pipe):
// B-pairs come straight from LDS.64; A is broadcast-packed with mov.b64 {a,a}.
// ---------------------------------------------------------------------------
#define BM  128
#define BN  128
#define BKK 8

__global__ __launch_bounds__(256) void gemm_kernel(
    const float* __restrict__ Wt,    // [COUT][RDIM] (weight flattened, r=c*9+k)
    const float* __restrict__ bias,  // [COUT]
    float* __restrict__ out)         // [B][COUT][P]
{
    __shared__ float As[2][BKK][BM];  // A stored k-major, m-contiguous
    __shared__ float Bs[2][BKK][BN];

    int tid = threadIdx.x;
    int bm = blockIdx.y * BM;
    int bn = blockIdx.x * BN;

    int a_row = tid >> 1;            // 0..127
    int a_col = (tid & 1) * 4;       // 0 or 4
    int b_row = tid >> 5;            // 0..7
    int b_col = (tid & 31) * 4;      // 0..124

    const float* Ag = Wt + (bm + a_row) * RDIM + a_col;
    const float* Bg = g_cols + b_row * NTOT + bn + b_col;

    // Prologue: load tile 0
    float4 at = *(const float4*)Ag;
    float4 bt = *(const float4*)Bg;
    As[0][a_col + 0][a_row] = at.x; As[0][a_col + 1][a_row] = at.y;
    As[0][a_col + 2][a_row] = at.z; As[0][a_col + 3][a_row] = at.w;
    *(float4*)&Bs[0][b_row][b_col] = bt;
    __syncthreads();

    int ty = tid >> 4, tx = tid & 15;

    unsigned long long acc[8][4];    // 8 rows x 4 packed col-pairs
    #pragma unroll
    for (int i = 0; i < 8; i++)
        #pragma unroll
        for (int j = 0; j < 4; j++) acc[i][j] = 0ull;

    int buf = 0;
    for (int kt = BKK; kt <= RDIM; kt += BKK) {
        bool last = (kt == RDIM);
        if (!last) {
            at = *(const float4*)(Ag + kt);
            bt = *(const float4*)(Bg + kt * NTOT);
        }
        #pragma unroll
        for (int kk = 0; kk < BKK; kk++) {
            float4 a0 = *(const float4*)&As[buf][kk][ty * 8];
            float4 a1 = *(const float4*)&As[buf][kk][ty * 8 + 4];
            const unsigned long long* bsp =
                (const unsigned long long*)&Bs[buf][kk][tx * 8];
            unsigned long long bp0 = bsp[0], bp1 = bsp[1],
                               bp2 = bsp[2], bp3 = bsp[3];
            float as8[8] = {a0.x, a0.y, a0.z, a0.w, a1.x, a1.y, a1.z, a1.w};
            #pragma unroll
            for (int i = 0; i < 8; i++) {
                unsigned long long ap;
                asm("mov.b64 %0, {%1, %1};"
                    : "=l"(ap) : "r"(__float_as_uint(as8[i])));
                asm("fma.rn.f32x2 %0, %1, %2, %0;" : "+l"(acc[i][0]) : "l"(ap), "l"(bp0));
                asm("fma.rn.f32x2 %0, %1, %2, %0;" : "+l"(acc[i][1]) : "l"(ap), "l"(bp1));
                asm("fma.rn.f32x2 %0, %1, %2, %0;" : "+l"(acc[i][2]) : "l"(ap), "l"(bp2));
                asm("fma.rn.f32x2 %0, %1, %2, %0;" : "+l"(acc[i][3]) : "l"(ap), "l"(bp3));
            }
        }
        buf ^= 1;
        if (!last) {
            As[buf][a_col + 0][a_row] = at.x; As[buf][a_col + 1][a_row] = at.y;
            As[buf][a_col + 2][a_row] = at.z; As[buf][a_col + 3][a_row] = at.w;
            *(float4*)&Bs[buf][b_row][b_col] = bt;
            __syncthreads();
        }
    }

    // Epilogue: n = bn + tx*8 + {0..7};  BN=128 divides 4096 so batch is
    // constant per block.
    int bb = bn >> 12;
    int p0 = (bn & 4095) + tx * 8;
    #pragma unroll
    for (int i = 0; i < 8; i++) {
        int co = bm + ty * 8 + i;
        float bi = bias[co];
        float* op = out + (bb * COUT_ + co) * P_ + p0;
        #pragma unroll
        for (int j = 0; j < 4; j++) {
            float lo = __uint_as_float((unsigned)(acc[i][j] & 0xffffffffull));
            float hi = __uint_as_float((unsigned)(acc[i][j] >> 32));
            float2 v = make_float2(lo + bi, hi + bi);
            *(float2*)(op + 2 * j) = v;
        }
    }
}

// ---------------------------------------------------------------------------
extern "C" void kernel_launch(void* const* d_in, const int* in_sizes, int n_in,
                              void* d_out, int out_size) {
    const float* x      = (const float*)d_in[0];  // [4,256,64,64]
    const float* offset = (const float*)d_in[1];  // [4,18,64,64]
    const float* mask   = (const float*)d_in[2];  // [4,9,64,64]
    const float* weight = (const float*)d_in[3];  // [256,256,3,3]
    const float* bias   = (const float*)d_in[4];  // [256]
    float* out = (float*)d_out;                   // [4,256,64,64]

    im2col_kernel<<<dim3(P_ / 128, K_, B_), 128>>>(x, offset, mask);
    gemm_kernel<<<dim3(NTOT / BN, COUT_ / BM), 256>>>(weight, bias, out);
}

// round 4
// speedup vs baseline: 1.9374x; 1.9374x over previous
#include <cuda_runtime.h>
#include <cuda_bf16.h>
#include <cstdint>

#define B_    4
#define CIN_  256
#define P_    4096
#define K_    9
#define RDIM  2304          // CIN*9
#define COUT_ 256
#define NTOT  16384         // B*P

// ---------------------------------------------------------------------------
// Device scratch (static — no cudaMalloc allowed)
// ---------------------------------------------------------------------------
__device__ __align__(128) __nv_bfloat16 g_hi[(size_t)RDIM * NTOT];
__device__ __align__(128) __nv_bfloat16 g_lo[(size_t)RDIM * NTOT];
__device__ __align__(128) __nv_bfloat16 g_whi[COUT_ * RDIM];
__device__ __align__(128) __nv_bfloat16 g_wlo[COUT_ * RDIM];

__device__ __forceinline__ uint32_t smem_u32(const void* p) {
    uint32_t a;
    asm("{ .reg .u64 t; cvta.to.shared.u64 t, %1; cvt.u32.u64 %0, t; }"
        : "=r"(a) : "l"(p));
    return a;
}

#define CP16(dst, src) \
    asm volatile("cp.async.cg.shared.global [%0], [%1], 16;" \
                 :: "r"(dst), "l"(src) : "memory")
#define CP_COMMIT() asm volatile("cp.async.commit_group;" ::: "memory")
#define CP_WAIT1()  asm volatile("cp.async.wait_group 1;" ::: "memory")

#define LDMX4(r0, r1, r2, r3, a) \
    asm volatile("ldmatrix.sync.aligned.m8n8.x4.shared.b16 {%0,%1,%2,%3}, [%4];" \
                 : "=r"(r0), "=r"(r1), "=r"(r2), "=r"(r3) : "r"(a))
#define LDMX4T(r0, r1, r2, r3, a) \
    asm volatile("ldmatrix.sync.aligned.m8n8.x4.trans.shared.b16 {%0,%1,%2,%3}, [%4];" \
                 : "=r"(r0), "=r"(r1), "=r"(r2), "=r"(r3) : "r"(a))

#define MMA16816(d, a, b0, b1) \
    asm volatile("mma.sync.aligned.m16n8k16.row.col.f32.bf16.bf16.f32 " \
                 "{%0,%1,%2,%3},{%4,%5,%6,%7},{%8,%9},{%0,%1,%2,%3};" \
                 : "+f"((d)[0]), "+f"((d)[1]), "+f"((d)[2]), "+f"((d)[3]) \
                 : "r"((a)[0]), "r"((a)[1]), "r"((a)[2]), "r"((a)[3]), \
                   "r"(b0), "r"(b1))

// ---------------------------------------------------------------------------
// Kernel 0: split weights into bf16 hi/lo
// ---------------------------------------------------------------------------
__global__ void wsplit_kernel(const float* __restrict__ w) {
    int i = blockIdx.x * blockDim.x + threadIdx.x;
    if (i >= COUT_ * RDIM) return;
    float v = w[i];
    __nv_bfloat16 h = __float2bfloat16(v);
    __nv_bfloat16 l = __float2bfloat16(v - __bfloat162float(h));
    g_whi[i] = h;
    g_wlo[i] = l;
}

// ---------------------------------------------------------------------------
// Kernel 1: fused sampling + im2col -> bf16 hi/lo cols  (layout [r][n])
// ---------------------------------------------------------------------------
__global__ void im2col_kernel(const float* __restrict__ x,
                              const float* __restrict__ offset,
                              const float* __restrict__ mask) {
    int p = blockIdx.x * blockDim.x + threadIdx.x;
    int k = blockIdx.y;
    int b = blockIdx.z;
    int oy = p >> 6, ox = p & 63;
    int kh = k / 3, kw = k - kh * 3;

    const float* offb = offset + (b * 18 + 2 * k) * P_;
    float dy = offb[p];
    float dx = offb[P_ + p];
    float m  = mask[(b * 9 + k) * P_ + p];

    float sy = (float)(oy - 1 + kh) + dy;
    float sx = (float)(ox - 1 + kw) + dx;
    float y0f = floorf(sy), x0f = floorf(sx);
    float wy = sy - y0f,    wx = sx - x0f;
    int y0 = (int)y0f, x0 = (int)x0f;
    int y1 = y0 + 1,   x1 = x0 + 1;

    bool vy0 = ((unsigned)y0 < 64u), vy1 = ((unsigned)y1 < 64u);
    bool vx0 = ((unsigned)x0 < 64u), vx1 = ((unsigned)x1 < 64u);
    int cy0 = min(max(y0, 0), 63), cy1 = min(max(y1, 0), 63);
    int cx0 = min(max(x0, 0), 63), cx1 = min(max(x1, 0), 63);
    int i00 = cy0 * 64 + cx0, i01 = cy0 * 64 + cx1;
    int i10 = cy1 * 64 + cx0, i11 = cy1 * 64 + cx1;

    float w00 = (1.f - wy) * (1.f - wx) * m; if (!(vy0 && vx0)) w00 = 0.f;
    float w01 = (1.f - wy) * wx * m;         if (!(vy0 && vx1)) w01 = 0.f;
    float w10 = wy * (1.f - wx) * m;         if (!(vy1 && vx0)) w10 = 0.f;
    float w11 = wy * wx * m;                 if (!(vy1 && vx1)) w11 = 0.f;

    const float* xb = x + b * (CIN_ * P_);
    size_t n = (size_t)b * P_ + p;

    #pragma unroll 4
    for (int c = 0; c < CIN_; c++) {
        const float* xp = xb + c * P_;
        float v = w00 * __ldg(xp + i00) + w01 * __ldg(xp + i01)
                + w10 * __ldg(xp + i10) + w11 * __ldg(xp + i11);
        __nv_bfloat16 h = __float2bfloat16(v);
        __nv_bfloat16 l = __float2bfloat16(v - __bfloat162float(h));
        size_t idx = (size_t)(c * 9 + k) * NTOT + n;
        g_hi[idx] = h;
        g_lo[idx] = l;
    }
}

// ---------------------------------------------------------------------------
// Kernel 2: bf16 split-precision GEMM via mma.sync (HMMA)
//   C[256 x 16384] = W[256 x 2304] * cols[2304 x 16384] + bias
//   CTA 128x128, K-chunk 32, 8 warps (2x4), warp tile 64x32, 3-stage cp.async.
// ---------------------------------------------------------------------------
#define BK      32
#define NCH     (RDIM / BK)       // 72
#define A_STRIDE 80               // bytes per m-row (64 data + 16 pad)
#define B_STRIDE 272              // bytes per k-row (256 data + 16 pad)
#define OFF_AH  0
#define OFF_AL  (128 * A_STRIDE)              // 10240
#define OFF_BH  (2 * 128 * A_STRIDE)          // 20480
#define OFF_BL  (OFF_BH + 32 * B_STRIDE)      // 29184
#define STAGE_BYTES (OFF_BL + 32 * B_STRIDE)  // 37888
#define SMEM_TOTAL (3 * STAGE_BYTES)          // 113664

__global__ __launch_bounds__(256, 1) void gemm_mma_kernel(
    const float* __restrict__ bias, float* __restrict__ out)
{
    extern __shared__ char smem[];
    const uint32_t sb0 = smem_u32(smem);
    const int tid = threadIdx.x;
    const int lane = tid & 31, wid = tid >> 5;
    const int warp_m = wid >> 2;          // 0..1  -> m offset *64
    const int warp_n = wid & 3;           // 0..3  -> n offset *32
    const int bm = blockIdx.y * 128;
    const int n0 = blockIdx.x * 128;

    // ldmatrix lane-address components
    const int lgrp = lane >> 3, lr = lane & 7;
    const int a_row   = ((lgrp & 1) << 3) + lr;   // 0..15
    const int a_chunk = lgrp >> 1;                // 0..1 (16B chunk within k16)
    const int b_krow  = ((lgrp & 1) << 3) + lr;   // 0..15
    const int b_col   = (warp_n << 5) + ((lgrp >> 1) << 3);  // n within tile

    const __nv_bfloat16* WH = g_whi + (size_t)bm * RDIM;
    const __nv_bfloat16* WL = g_wlo + (size_t)bm * RDIM;

    // cp.async indexing (per thread, 2 iters each)
    const int ar = tid >> 2, ac = tid & 3;     // A: 4 x 16B per 64B row
    const int br = tid >> 4, bc = tid & 15;    // B: 16 x 16B per 256B row

    float d[4][4][4];
    #pragma unroll
    for (int i = 0; i < 4; i++)
        #pragma unroll
        for (int j = 0; j < 4; j++)
            #pragma unroll
            for (int q = 0; q < 4; q++) d[i][j][q] = 0.f;

    // ---- stage loader ----
    auto load_stage = [&](int ch) {
        const int kc0 = ch * BK;
        const uint32_t st = sb0 + (ch % 3) * STAGE_BYTES;
        const __nv_bfloat16* wh = WH + kc0;
        const __nv_bfloat16* wl = WL + kc0;
        const __nv_bfloat16* bh = g_hi + (size_t)kc0 * NTOT + n0;
        const __nv_bfloat16* bl = g_lo + (size_t)kc0 * NTOT + n0;
        #pragma unroll
        for (int i = 0; i < 2; i++) {
            int r = ar + i * 64;
            uint32_t dsta = st + OFF_AH + r * A_STRIDE + ac * 16;
            const __nv_bfloat16* sa = wh + (size_t)r * RDIM + ac * 8;
            CP16(dsta, sa);
            CP16(dsta + (OFF_AL - OFF_AH), wl + (size_t)r * RDIM + ac * 8);
        }
        #pragma unroll
        for (int i = 0; i < 2; i++) {
            int r = br + i * 16;
            uint32_t dstb = st + OFF_BH + r * B_STRIDE + bc * 16;
            CP16(dstb, bh + (size_t)r * NTOT + bc * 8);
            CP16(dstb + (OFF_BL - OFF_BH), bl + (size_t)r * NTOT + bc * 8);
        }
    };

    load_stage(0); CP_COMMIT();
    load_stage(1); CP_COMMIT();

    for (int ch = 0; ch < NCH; ch++) {
        CP_WAIT1();
        __syncthreads();
        if (ch + 2 < NCH) load_stage(ch + 2);
        CP_COMMIT();

        const uint32_t st = sb0 + (ch % 3) * STAGE_BYTES;
        const uint32_t aHbase = st + OFF_AH +
            (warp_m * 64 + a_row) * A_STRIDE + a_chunk * 16;
        const uint32_t bHbase = st + OFF_BH + b_krow * B_STRIDE + b_col * 2;

        #pragma unroll
        for (int s = 0; s < 2; s++) {      // two k16 steps
            uint32_t afh[4][4], afl[4][4], bfh[2][4], bfl[2][4];
            #pragma unroll
            for (int i = 0; i < 4; i++) {
                uint32_t aa = aHbase + i * (16 * A_STRIDE) + s * 32;
                LDMX4(afh[i][0], afh[i][1], afh[i][2], afh[i][3], aa);
                LDMX4(afl[i][0], afl[i][1], afl[i][2], afl[i][3],
                      aa + (OFF_AL - OFF_AH));
            }
            #pragma unroll
            for (int g = 0; g < 2; g++) {
                uint32_t ba = bHbase + s * (16 * B_STRIDE) + g * 32;
                LDMX4T(bfh[g][0], bfh[g][1], bfh[g][2], bfh[g][3], ba);
                LDMX4T(bfl[g][0], bfl[g][1], bfl[g][2], bfl[g][3],
                       ba + (OFF_BL - OFF_BH));
            }
            #pragma unroll
            for (int i = 0; i < 4; i++) {
                #pragma unroll
                for (int g = 0; g < 2; g++) {
                    #pragma unroll
                    for (int jn = 0; jn < 2; jn++) {
                        float* dd = d[i][g * 2 + jn];
                        MMA16816(dd, afh[i], bfh[g][jn * 2], bfh[g][jn * 2 + 1]);
                        MMA16816(dd, afh[i], bfl[g][jn * 2], bfl[g][jn * 2 + 1]);
                        MMA16816(dd, afl[i], bfh[g][jn * 2], bfh[g][jn * 2 + 1]);
                    }
                }
            }
        }
    }

    // ---- epilogue ----
    const int row0 = lane >> 2, col0 = (lane & 3) * 2;
    const int bb = n0 >> 12;
    const int pbase = (n0 & 4095) + warp_n * 32 + col0;
    #pragma unroll
    for (int i = 0; i < 4; i++) {
        int co = bm + warp_m * 64 + i * 16 + row0;
        float bi0 = __ldg(bias + co);
        float bi1 = __ldg(bias + co + 8);
        float* o0 = out + ((size_t)(bb * COUT_ + co)) * P_ + pbase;
        float* o1 = o0 + 8 * P_;
        #pragma unroll
        for (int j = 0; j < 4; j++) {
            float2 v0 = make_float2(d[i][j][0] + bi0, d[i][j][1] + bi0);
            float2 v1 = make_float2(d[i][j][2] + bi1, d[i][j][3] + bi1);
            *(float2*)(o0 + j * 8) = v0;
            *(float2*)(o1 + j * 8) = v1;
        }
    }
}

// ---------------------------------------------------------------------------
extern "C" void kernel_launch(void* const* d_in, const int* in_sizes, int n_in,
                              void* d_out, int out_size) {
    const float* x      = (const float*)d_in[0];
    const float* offset = (const float*)d_in[1];
    const float* mask   = (const float*)d_in[2];
    const float* weight = (const float*)d_in[3];
    const float* bias   = (const float*)d_in[4];
    float* out = (float*)d_out;

    cudaFuncSetAttribute(gemm_mma_kernel,
                         cudaFuncAttributeMaxDynamicSharedMemorySize, SMEM_TOTAL);

    wsplit_kernel<<<(COUT_ * RDIM + 255) / 256, 256>>>(weight);
    im2col_kernel<<<dim3(P_ / 128, K_, B_), 128>>>(x, offset, mask);
    gemm_mma_kernel<<<dim3(NTOT / 128, COUT_ / 128), 256, SMEM_TOTAL>>>(bias, out);
}